// round 7
// baseline (speedup 1.0000x reference)
#include <cuda_runtime.h>
#include <cuda_fp16.h>
#include <cstdint>

// ---------------------------------------------------------------------------
// GCN_8796093022507: 2-layer GCN, dropout 0.6, N=100000, E=6.4M.
// R7: revert R6 smem staging (latency-exposed). R5 structure + deeper MLP:
//  - edge passes: 4 edges/thread, int4 index loads, batched independent gathers
//  - deg pass: 8 edges/thread
//  - acc zeroing folded into node1/node2
// fp16 payload tables (L1-resident). PRNG: threefry partitionable (verified).
// ---------------------------------------------------------------------------

#define NMAX 100000

__device__ int      g_deg[NMAX];
__device__ float    g_dinv[NMAX];
__device__ __align__(16) __half g_u[NMAX];   // layer1 payload: dropout1(x)*dinv
__device__ __align__(16) __half g_w[NMAX];   // layer2 payload: t*dinv
__device__ float    g_acc1[NMAX];
__device__ float    g_acc2[NMAX];
__device__ unsigned g_key[4];
__device__ int      g_is64;

__device__ __forceinline__ uint2 tf2x32(unsigned k0, unsigned k1,
                                        unsigned x0, unsigned x1) {
  unsigned k2 = k0 ^ k1 ^ 0x1BD11BDAu;
  x0 += k0; x1 += k1;
#define TFR(r) { x0 += x1; x1 = (x1 << (r)) | (x1 >> (32 - (r))); x1 ^= x0; }
  TFR(13) TFR(15) TFR(26) TFR(6)
  x0 += k1; x1 += k2 + 1u;
  TFR(17) TFR(29) TFR(16) TFR(24)
  x0 += k2; x1 += k0 + 2u;
  TFR(13) TFR(15) TFR(26) TFR(6)
  x0 += k0; x1 += k1 + 3u;
  TFR(17) TFR(29) TFR(16) TFR(24)
  x0 += k1; x1 += k2 + 4u;
  TFR(13) TFR(15) TFR(26) TFR(6)
  x0 += k2; x1 += k0 + 5u;
#undef TFR
  return make_uint2(x0, x1);
}

__device__ __forceinline__ bool keep40(unsigned k0, unsigned k1, unsigned i) {
  uint2 z = tf2x32(k0, k1, 0u, i);
  unsigned bits = z.x ^ z.y;
  float u = __uint_as_float((bits >> 9) | 0x3F800000u) - 1.0f;
  return u < 0.4f;
}

__global__ void k_init(const void* ei, int E, int N) {
  int i = blockIdx.x * blockDim.x + threadIdx.x;
  if (i < N) g_deg[i] = 0;
  if (i == 0) {
    const long long* p = (const long long*)ei;
    bool ok64 = true;
    for (int k = 0; k < 4; k++) {
      long long v = p[k];
      if (v < 0 || v >= (long long)N) ok64 = false;
    }
    g_is64 = ok64 ? 1 : 0;
    uint2 ka = tf2x32(0u, 42u, 0u, 0u);
    uint2 kb = tf2x32(0u, 42u, 0u, 1u);
    g_key[0] = ka.x; g_key[1] = ka.y;
    g_key[2] = kb.x; g_key[3] = kb.y;
  }
}

// In-degree histogram over the dst row, 8 edges per thread (2x int4).
__global__ void k_deg(const void* ei, int nocts, int E, int N) {
  int i = blockIdx.x * blockDim.x + threadIdx.x;
  if (i >= nocts) return;
  long long e0 = 8LL * i;
  if (g_is64) {
    const long long* dstr = (const long long*)ei + E;
    for (int k = 0; k < 8 && e0 + k < E; k++) {
      int d = (int)dstr[e0 + k];
      if ((unsigned)d < (unsigned)N) atomicAdd(&g_deg[d], 1);
    }
  } else {
    const int* dstr = (const int*)ei + E;
    if (e0 + 7 < E) {
      int4 a = ((const int4*)dstr)[2 * i];
      int4 b = ((const int4*)dstr)[2 * i + 1];
      atomicAdd(&g_deg[a.x], 1); atomicAdd(&g_deg[a.y], 1);
      atomicAdd(&g_deg[a.z], 1); atomicAdd(&g_deg[a.w], 1);
      atomicAdd(&g_deg[b.x], 1); atomicAdd(&g_deg[b.y], 1);
      atomicAdd(&g_deg[b.z], 1); atomicAdd(&g_deg[b.w], 1);
    } else {
      for (int k = 0; k < 8 && e0 + k < E; k++)
        atomicAdd(&g_deg[dstr[e0 + k]], 1);
    }
  }
}

__global__ void k_node1(const float* __restrict__ x, int N) {
  int i = blockIdx.x * blockDim.x + threadIdx.x;
  if (i >= N) return;
  g_acc1[i] = 0.0f;
  int d = g_deg[i];
  float dinv = (d > 0) ? rsqrtf((float)d) : 0.0f;
  g_dinv[i] = dinv;
  float u = keep40(g_key[0], g_key[1], (unsigned)i) ? x[i] * 2.5f * dinv : 0.0f;
  g_u[i] = __float2half(u);
}

// Scatter payload[src] into acc[dst]; 4 edges per thread, batched gathers.
// LAYER 0: g_u -> g_acc1, LAYER 1: g_w -> g_acc2.
template <int LAYER>
__global__ void k_edge(const void* ei, int nquads, int E) {
  int i = blockIdx.x * blockDim.x + threadIdx.x;
  if (i >= nquads) return;
  const __half* tab = (LAYER == 0) ? g_u : g_w;
  float* acc = (LAYER == 0) ? g_acc1 : g_acc2;
  long long e0 = 4LL * i;
  if (!g_is64 && e0 + 3 < E) {
    const int* p = (const int*)ei;
    int4 s4 = ((const int4*)p)[i];
    int4 d4 = ((const int4*)(p + E))[i];
    // batched independent gathers (front-load MLP)
    __half h0 = __ldg(&tab[s4.x]);
    __half h1 = __ldg(&tab[s4.y]);
    __half h2 = __ldg(&tab[s4.z]);
    __half h3 = __ldg(&tab[s4.w]);
    float v0 = __half2float(h0);
    float v1 = __half2float(h1);
    float v2 = __half2float(h2);
    float v3 = __half2float(h3);
    if (v0 != 0.0f) atomicAdd(&acc[d4.x], v0);
    if (v1 != 0.0f) atomicAdd(&acc[d4.y], v1);
    if (v2 != 0.0f) atomicAdd(&acc[d4.z], v2);
    if (v3 != 0.0f) atomicAdd(&acc[d4.w], v3);
  } else if (g_is64) {
    const long long* p = (const long long*)ei;
    for (int k = 0; k < 4 && e0 + k < E; k++) {
      int s = (int)p[e0 + k], d = (int)p[E + e0 + k];
      float v = __half2float(tab[s]);
      if (v != 0.0f) atomicAdd(&acc[d], v);
    }
  } else {
    const int* p = (const int*)ei;
    for (int k = 0; k < 4 && e0 + k < E; k++) {
      int s = p[e0 + k], d = p[E + e0 + k];
      float v = __half2float(tab[s]);
      if (v != 0.0f) atomicAdd(&acc[d], v);
    }
  }
}

__global__ void k_node2(const float* __restrict__ W1, const float* __restrict__ b1,
                        const float* __restrict__ W2, int N) {
  int tid = blockIdx.x * blockDim.x + threadIdx.x;
  int n = tid >> 4, j = tid & 15;
  if (n >= N) return;
  float dinv = g_dinv[n];
  float s1 = g_acc1[n] * dinv;                                 // finish layer1
  float v = fmaxf(s1 * __ldg(&W1[j]) + __ldg(&b1[j]), 0.0f);   // relu
  unsigned i = (unsigned)n * 16u + (unsigned)j;
  v = keep40(g_key[2], g_key[3], i) ? v * 2.5f : 0.0f;         // dropout2
  v *= __ldg(&W2[j]);
  #pragma unroll
  for (int off = 8; off; off >>= 1)
    v += __shfl_xor_sync(0xFFFFFFFFu, v, off, 16);
  if (j == 0) {
    g_w[n] = __float2half(v * dinv);                           // payload = t*dinv
    g_acc2[n] = 0.0f;
  }
}

__global__ void k_node3(const float* __restrict__ b2, float* __restrict__ out, int N) {
  int i = blockIdx.x * blockDim.x + threadIdx.x;
  if (i >= N) return;
  out[i] = g_acc2[i] * g_dinv[i] + b2[0];
}

extern "C" void kernel_launch(void* const* d_in, const int* in_sizes, int n_in,
                              void* d_out, int out_size) {
  const float* x  = (const float*)d_in[0];
  const void*  ei = d_in[1];
  const float* W1 = (const float*)d_in[2];
  const float* b1 = (const float*)d_in[3];
  const float* W2 = (const float*)d_in[4];
  const float* b2 = (const float*)d_in[5];
  float* out = (float*)d_out;

  int N = in_sizes[0];
  int E = in_sizes[1] / 2;

  const int TB = 256;
  int nblkN   = (N + TB - 1) / TB;
  int nquads  = (E + 3) / 4;
  int nocts   = (E + 7) / 8;
  int nblkQ   = (nquads + TB - 1) / TB;
  int nblkO   = (nocts + TB - 1) / TB;
  int nblkN16 = (N * 16 + TB - 1) / TB;

  k_init   <<<nblkN,  TB>>>(ei, E, N);
  k_deg    <<<nblkO,  TB>>>(ei, nocts, E, N);
  k_node1  <<<nblkN,  TB>>>(x, N);
  k_edge<0><<<nblkQ,  TB>>>(ei, nquads, E);
  k_node2  <<<nblkN16, TB>>>(W1, b1, W2, N);
  k_edge<1><<<nblkQ,  TB>>>(ei, nquads, E);
  k_node3  <<<nblkN,  TB>>>(b2, out, N);
}

// round 8
// speedup vs baseline: 1.0217x; 1.0217x over previous
#include <cuda_runtime.h>
#include <cuda_fp16.h>
#include <cstdint>

// ---------------------------------------------------------------------------
// GCN_8796093022507: 2-layer GCN, dropout 0.6, N=100000, E=6.4M.
// R8: revert to R5 structure (best measured, 119.5us) — 2 edges/thread edge
// passes, 4 edges/thread deg, fp16 payload tables, rank-1 factorization.
// Polish: __ldg gathers, ushort zero-test, launch_bounds.
// Model: passes are REDG-lane bound (1.29 cyc/lane/SM spread); structure is at
// its floor; R6 (smem staging) and R7 (deeper ILP) both regressed.
// PRNG: JAX threefry2x32, partitionable (verified rel_err ~3e-7 fp32 path).
// ---------------------------------------------------------------------------

#define NMAX 100000

__device__ int      g_deg[NMAX];
__device__ float    g_dinv[NMAX];
__device__ __align__(16) __half g_u[NMAX];   // layer1 payload: dropout1(x)*dinv
__device__ __align__(16) __half g_w[NMAX];   // layer2 payload: t*dinv
__device__ float    g_acc1[NMAX];
__device__ float    g_acc2[NMAX];
__device__ unsigned g_key[4];
__device__ int      g_is64;

__device__ __forceinline__ uint2 tf2x32(unsigned k0, unsigned k1,
                                        unsigned x0, unsigned x1) {
  unsigned k2 = k0 ^ k1 ^ 0x1BD11BDAu;
  x0 += k0; x1 += k1;
#define TFR(r) { x0 += x1; x1 = (x1 << (r)) | (x1 >> (32 - (r))); x1 ^= x0; }
  TFR(13) TFR(15) TFR(26) TFR(6)
  x0 += k1; x1 += k2 + 1u;
  TFR(17) TFR(29) TFR(16) TFR(24)
  x0 += k2; x1 += k0 + 2u;
  TFR(13) TFR(15) TFR(26) TFR(6)
  x0 += k0; x1 += k1 + 3u;
  TFR(17) TFR(29) TFR(16) TFR(24)
  x0 += k1; x1 += k2 + 4u;
  TFR(13) TFR(15) TFR(26) TFR(6)
  x0 += k2; x1 += k0 + 5u;
#undef TFR
  return make_uint2(x0, x1);
}

__device__ __forceinline__ bool keep40(unsigned k0, unsigned k1, unsigned i) {
  uint2 z = tf2x32(k0, k1, 0u, i);
  unsigned bits = z.x ^ z.y;
  float u = __uint_as_float((bits >> 9) | 0x3F800000u) - 1.0f;
  return u < 0.4f;
}

__global__ void k_init(const void* ei, int E, int N) {
  int i = blockIdx.x * blockDim.x + threadIdx.x;
  if (i < N) { g_deg[i] = 0; g_acc1[i] = 0.0f; g_acc2[i] = 0.0f; }
  if (i == 0) {
    const long long* p = (const long long*)ei;
    bool ok64 = true;
    for (int k = 0; k < 4; k++) {
      long long v = p[k];
      if (v < 0 || v >= (long long)N) ok64 = false;
    }
    g_is64 = ok64 ? 1 : 0;
    uint2 ka = tf2x32(0u, 42u, 0u, 0u);
    uint2 kb = tf2x32(0u, 42u, 0u, 1u);
    g_key[0] = ka.x; g_key[1] = ka.y;
    g_key[2] = kb.x; g_key[3] = kb.y;
  }
}

// In-degree histogram over the dst row, 4 edges per thread (int4).
__global__ void __launch_bounds__(256) k_deg(const void* ei, int nquads, int E, int N) {
  int i = blockIdx.x * blockDim.x + threadIdx.x;
  if (i >= nquads) return;
  int e0 = 4 * i;
  if (g_is64) {
    const long long* dstr = (const long long*)ei + E;
    for (int k = 0; k < 4 && e0 + k < E; k++) {
      int d = (int)dstr[e0 + k];
      if ((unsigned)d < (unsigned)N) atomicAdd(&g_deg[d], 1);
    }
  } else {
    const int* dstr = (const int*)ei + E;
    if (e0 + 3 < E) {
      int4 d4 = ((const int4*)dstr)[i];
      atomicAdd(&g_deg[d4.x], 1);
      atomicAdd(&g_deg[d4.y], 1);
      atomicAdd(&g_deg[d4.z], 1);
      atomicAdd(&g_deg[d4.w], 1);
    } else {
      for (int k = 0; k < 4 && e0 + k < E; k++)
        atomicAdd(&g_deg[dstr[e0 + k]], 1);
    }
  }
}

__global__ void k_node1(const float* __restrict__ x, int N) {
  int i = blockIdx.x * blockDim.x + threadIdx.x;
  if (i >= N) return;
  int d = g_deg[i];
  float dinv = (d > 0) ? rsqrtf((float)d) : 0.0f;
  g_dinv[i] = dinv;
  float u = keep40(g_key[0], g_key[1], (unsigned)i) ? x[i] * 2.5f * dinv : 0.0f;
  g_u[i] = __float2half(u);
}

// Scatter payload[src] into acc[dst]; 2 edges/thread (R5 proven-best config).
// LAYER 0: g_u -> g_acc1, LAYER 1: g_w -> g_acc2.
template <int LAYER>
__global__ void __launch_bounds__(256) k_edge(const void* ei, int npairs, int E) {
  int i = blockIdx.x * blockDim.x + threadIdx.x;
  if (i >= npairs) return;
  const __half* tab = (LAYER == 0) ? g_u : g_w;
  float* acc = (LAYER == 0) ? g_acc1 : g_acc2;
  int e0 = 2 * i;
  if (!g_is64) {
    const int* p = (const int*)ei;
    if (e0 + 1 < E) {
      int2 sv = ((const int2*)p)[i];
      int2 dv = ((const int2*)(p + E))[i];
      // batched independent gathers; zero-test on raw fp16 bits
      unsigned short b0 = __ldg((const unsigned short*)&tab[sv.x]);
      unsigned short b1 = __ldg((const unsigned short*)&tab[sv.y]);
      if (b0) atomicAdd(&acc[dv.x], __half2float(__ushort_as_half(b0)));
      if (b1) atomicAdd(&acc[dv.y], __half2float(__ushort_as_half(b1)));
    } else {
      int s = p[e0], d = p[E + e0];
      unsigned short b = __ldg((const unsigned short*)&tab[s]);
      if (b) atomicAdd(&acc[d], __half2float(__ushort_as_half(b)));
    }
  } else {
    const long long* p = (const long long*)ei;
    for (int k = 0; k < 2 && e0 + k < E; k++) {
      int s = (int)p[e0 + k], d = (int)p[E + e0 + k];
      float v = __half2float(tab[s]);
      if (v != 0.0f) atomicAdd(&acc[d], v);
    }
  }
}

__global__ void k_node2(const float* __restrict__ W1, const float* __restrict__ b1,
                        const float* __restrict__ W2, int N) {
  int tid = blockIdx.x * blockDim.x + threadIdx.x;
  int n = tid >> 4, j = tid & 15;
  if (n >= N) return;
  float dinv = g_dinv[n];
  float s1 = g_acc1[n] * dinv;                                 // finish layer1
  float v = fmaxf(s1 * __ldg(&W1[j]) + __ldg(&b1[j]), 0.0f);   // relu
  unsigned i = (unsigned)n * 16u + (unsigned)j;
  v = keep40(g_key[2], g_key[3], i) ? v * 2.5f : 0.0f;         // dropout2
  v *= __ldg(&W2[j]);
  #pragma unroll
  for (int off = 8; off; off >>= 1)
    v += __shfl_xor_sync(0xFFFFFFFFu, v, off, 16);
  if (j == 0) g_w[n] = __float2half(v * dinv);                 // payload = t*dinv
}

__global__ void k_node3(const float* __restrict__ b2, float* __restrict__ out, int N) {
  int i = blockIdx.x * blockDim.x + threadIdx.x;
  if (i >= N) return;
  out[i] = g_acc2[i] * g_dinv[i] + b2[0];
}

extern "C" void kernel_launch(void* const* d_in, const int* in_sizes, int n_in,
                              void* d_out, int out_size) {
  const float* x  = (const float*)d_in[0];
  const void*  ei = d_in[1];
  const float* W1 = (const float*)d_in[2];
  const float* b1 = (const float*)d_in[3];
  const float* W2 = (const float*)d_in[4];
  const float* b2 = (const float*)d_in[5];
  float* out = (float*)d_out;

  int N = in_sizes[0];
  int E = in_sizes[1] / 2;

  const int TB = 256;
  int nblkN   = (N + TB - 1) / TB;
  int npairs  = (E + 1) / 2;
  int nquads  = (E + 3) / 4;
  int nblkP   = (npairs + TB - 1) / TB;
  int nblkQ   = (nquads + TB - 1) / TB;
  int nblkN16 = (N * 16 + TB - 1) / TB;

  k_init   <<<nblkN,  TB>>>(ei, E, N);
  k_deg    <<<nblkQ,  TB>>>(ei, nquads, E, N);
  k_node1  <<<nblkN,  TB>>>(x, N);
  k_edge<0><<<nblkP,  TB>>>(ei, npairs, E);
  k_node2  <<<nblkN16, TB>>>(W1, b1, W2, N);
  k_edge<1><<<nblkP,  TB>>>(ei, npairs, E);
  k_node3  <<<nblkN,  TB>>>(b2, out, N);
}